// round 15
// baseline (speedup 1.0000x reference)
#include <cuda_runtime.h>
#include <cuda_bf16.h>
#include <math.h>
#include <stdint.h>

// Problem constants
#define BATCH 32
#define SEQ   512
#define IN_D  512
#define HID   1024
#define G3    3072   // 3*HID
#define NCTA  128    // persistent scan grid size

typedef unsigned long long ull;

__device__ __forceinline__ uint32_t smem_u32(const void* p) {
    uint32_t a;
    asm("{ .reg .u64 t; cvta.to.shared.u64 t, %1; cvt.u32.u64 %0, t; }" : "=r"(a) : "l"(p));
    return a;
}

// mma.sync / ldmatrix / cp.async (baseline ISA, works on sm_103 target)
#define LDSM_X4(r0, r1, r2, r3, addr) \
    asm volatile("ldmatrix.sync.aligned.m8n8.x4.shared.b16 {%0,%1,%2,%3}, [%4];" \
        : "=r"(r0), "=r"(r1), "=r"(r2), "=r"(r3) : "r"(addr))
#define LDSM_X2(r0, r1, addr) \
    asm volatile("ldmatrix.sync.aligned.m8n8.x2.shared.b16 {%0,%1}, [%2];" \
        : "=r"(r0), "=r"(r1) : "r"(addr))
#define MMA_BF16(d, a, b) \
    asm volatile("mma.sync.aligned.m16n8k16.row.col.f32.bf16.bf16.f32 " \
        "{%0,%1,%2,%3}, {%4,%5,%6,%7}, {%8,%9}, {%0,%1,%2,%3};" \
        : "+f"((d)[0]), "+f"((d)[1]), "+f"((d)[2]), "+f"((d)[3]) \
        : "r"((a)[0]), "r"((a)[1]), "r"((a)[2]), "r"((a)[3]), "r"((b)[0]), "r"((b)[1]))
#define CP16(dst, src) \
    asm volatile("cp.async.cg.shared.global [%0], [%1], 16;" :: "r"(dst), "l"(src))
#define CP_COMMIT() asm volatile("cp.async.commit_group;" ::: "memory")
#define CP_WAIT0()  asm volatile("cp.async.wait_group 0;" ::: "memory")
#define CP_WAIT1()  asm volatile("cp.async.wait_group 1;" ::: "memory")

// ---------------------------------------------------------------------------
// Scratch (device globals)
// ---------------------------------------------------------------------------
__device__ float g_gx[(size_t)SEQ * BATCH * G3];
__device__ float g_y0[(size_t)SEQ * BATCH * HID];
__device__ float g_y1[(size_t)SEQ * BATCH * HID];
__device__ __nv_bfloat16 g_ah[(size_t)SEQ * BATCH * HID];  // A hi [M][K] row-major
__device__ __nv_bfloat16 g_al[(size_t)SEQ * BATCH * HID];  // A lo
__device__ __nv_bfloat16 g_wh[(size_t)G3 * HID];           // W hi [N][K] row-major
__device__ __nv_bfloat16 g_wl[(size_t)G3 * HID];           // W lo
__device__ __align__(16) __nv_bfloat16 g_hb[2][64 * 512];  // h hi, double-buffered, chunked [ch][b][16]
__device__ __align__(16) __nv_bfloat16 g_hl[2][64 * 512];  // h lo

// per-producer-CTA flag slots: group g's 16 slots at [g*32 .. g*32+15] (128B group stride)
__device__ unsigned g_sflag0[8 * 32];   // scan-0 flags
__device__ unsigned g_sflag1[8 * 32];   // scan-1 flags

// final-barrier state (used once per scan; gens monotonic, counts self-reset)
__device__ unsigned g_gcnt[16 * 64];
__device__ unsigned g_ggen[16 * 64];
__device__ unsigned g_rcnt;
__device__ unsigned g_rgen;

// ---------------------------------------------------------------------------
// fp32 -> (hi, lo) bf16 split.  Row m of src at (m>>5)*s0 + (m&31)*s1.
// ---------------------------------------------------------------------------
__global__ void conv_split(const float* __restrict__ src, int s0, int s1, int kbits,
                           size_t total, __nv_bfloat16* __restrict__ hi,
                           __nv_bfloat16* __restrict__ lo)
{
    const size_t km = ((size_t)1 << kbits) - 1;
    for (size_t idx = (size_t)blockIdx.x * blockDim.x + threadIdx.x; idx < total;
         idx += (size_t)gridDim.x * blockDim.x) {
        size_t m = idx >> kbits;
        int k = (int)(idx & km);
        float v = src[(m >> 5) * (size_t)s0 + (m & 31) * (size_t)s1 + k];
        __nv_bfloat16 h = __float2bfloat16(v);
        hi[idx] = h;
        lo[idx] = __float2bfloat16(v - __bfloat162float(h));
    }
}

// ---------------------------------------------------------------------------
// mma.sync split-bf16 GEMM (NT), 3-stage cp.async pipeline — unchanged R14
// ---------------------------------------------------------------------------
#define TPAD 40
#define TILE_BYTES (128 * TPAD * 2)
#define STAGE_BYTES (4 * TILE_BYTES)   // 40960
#define GEMM_SMEM (3 * STAGE_BYTES)    // 122880

__global__ __launch_bounds__(256)
void gemm_mma(const __nv_bfloat16* __restrict__ Ah, const __nv_bfloat16* __restrict__ Al,
              const __nv_bfloat16* __restrict__ Wh, const __nv_bfloat16* __restrict__ Wl,
              const float* __restrict__ bias, float* __restrict__ C,
              int K, int c_s0, int c_s1)
{
    extern __shared__ char smem[];
    const uint32_t sb = smem_u32(smem);

    const int tid  = threadIdx.x;
    const int wid  = tid >> 5;
    const int lane = tid & 31;
    const int wm   = wid >> 2;
    const int wn   = wid & 3;
    const int bm   = blockIdx.y * 128;
    const int bn   = blockIdx.x * 128;

    const __nv_bfloat16* srcs[4] = { Ah + (size_t)bm * K, Al + (size_t)bm * K,
                                     Wh + (size_t)bn * K, Wl + (size_t)bn * K };

    const int c0 = tid, c1 = tid + 256;
    const int r0 = c0 >> 2, q0 = c0 & 3;
    const int r1 = c1 >> 2, q1 = c1 & 3;

    float acc[4][4][4];
#pragma unroll
    for (int m = 0; m < 4; m++)
#pragma unroll
        for (int n = 0; n < 4; n++)
#pragma unroll
            for (int v = 0; v < 4; v++) acc[m][n][v] = 0.f;

    const int KT = K >> 5;

#pragma unroll
    for (int p = 0; p < 2; p++) {
        const uint32_t stg = sb + p * STAGE_BYTES;
        const int k0 = p << 5;
#pragma unroll
        for (int t = 0; t < 4; t++) {
            const uint32_t db = stg + t * TILE_BYTES;
            CP16(db + r0 * (TPAD * 2) + q0 * 16, srcs[t] + (size_t)r0 * K + k0 + q0 * 8);
            CP16(db + r1 * (TPAD * 2) + q1 * 16, srcs[t] + (size_t)r1 * K + k0 + q1 * 8);
        }
        CP_COMMIT();
    }

    const int a_row = (lane & 15);
    const int a_colh = (lane >> 4) * 8;
    const int b_row = (lane & 7);
    const int b_colh = ((lane >> 3) & 1) * 8;

    int bufi = 0;
    for (int kt = 0; kt < KT; kt++) {
        if (kt == KT - 1) { CP_WAIT0(); } else { CP_WAIT1(); }
        __syncthreads();

        const uint32_t buf = sb + bufi * STAGE_BYTES;

        if (kt + 2 < KT) {
            const int k0 = (kt + 2) << 5;
            int nb = bufi + 2; if (nb >= 3) nb -= 3;
            const uint32_t nbuf = sb + nb * STAGE_BYTES;
#pragma unroll
            for (int t = 0; t < 4; t++) {
                const uint32_t db = nbuf + t * TILE_BYTES;
                CP16(db + r0 * (TPAD * 2) + q0 * 16, srcs[t] + (size_t)r0 * K + k0 + q0 * 8);
                CP16(db + r1 * (TPAD * 2) + q1 * 16, srcs[t] + (size_t)r1 * K + k0 + q1 * 8);
            }
            CP_COMMIT();
        }

#pragma unroll
        for (int k16 = 0; k16 < 2; k16++) {
            uint32_t ah4[4][4], al4[4][4], bh2[4][2], bl2[4][2];
#pragma unroll
            for (int m = 0; m < 4; m++) {
                const uint32_t arow = wm * 64 + m * 16 + a_row;
                const uint32_t acol = k16 * 16 + a_colh;
                const uint32_t aoff = arow * (TPAD * 2) + acol * 2;
                LDSM_X4(ah4[m][0], ah4[m][1], ah4[m][2], ah4[m][3], buf + 0 * TILE_BYTES + aoff);
                LDSM_X4(al4[m][0], al4[m][1], al4[m][2], al4[m][3], buf + 1 * TILE_BYTES + aoff);
            }
#pragma unroll
            for (int n = 0; n < 4; n++) {
                const uint32_t brow = wn * 32 + n * 8 + b_row;
                const uint32_t bcol = k16 * 16 + b_colh;
                const uint32_t boff = brow * (TPAD * 2) + bcol * 2;
                LDSM_X2(bh2[n][0], bh2[n][1], buf + 2 * TILE_BYTES + boff);
                LDSM_X2(bl2[n][0], bl2[n][1], buf + 3 * TILE_BYTES + boff);
            }
#pragma unroll
            for (int m = 0; m < 4; m++)
#pragma unroll
                for (int n = 0; n < 4; n++) {
                    MMA_BF16(acc[m][n], ah4[m], bh2[n]);
                    MMA_BF16(acc[m][n], ah4[m], bl2[n]);
                    MMA_BF16(acc[m][n], al4[m], bh2[n]);
                }
        }
        if (++bufi >= 3) bufi = 0;
    }

    const int qid = lane >> 2;
    const int qtr = lane & 3;
#pragma unroll
    for (int m = 0; m < 4; m++) {
        const int ra = bm + wm * 64 + m * 16 + qid;
        const int rb = ra + 8;
        float* crowa = C + (size_t)(ra >> 5) * c_s0 + (size_t)(ra & 31) * c_s1;
        float* crowb = C + (size_t)(rb >> 5) * c_s0 + (size_t)(rb & 31) * c_s1;
#pragma unroll
        for (int n = 0; n < 4; n++) {
            const int col = bn + wn * 32 + n * 8 + qtr * 2;
            const float bv0 = bias[col], bv1 = bias[col + 1];
            float2 va, vb;
            va.x = acc[m][n][0] + bv0; va.y = acc[m][n][1] + bv1;
            vb.x = acc[m][n][2] + bv0; vb.y = acc[m][n][3] + bv1;
            *(float2*)(crowa + col) = va;
            *(float2*)(crowb + col) = vb;
        }
    }
}

// ---------------------------------------------------------------------------
// grid-wide barrier — two-level tree. Used ONCE per scan (flag reset).
// ---------------------------------------------------------------------------
__device__ __forceinline__ void grid_barrier()
{
    __syncthreads();
    if (threadIdx.x == 0) {
        const int g = blockIdx.x >> 3;
        volatile unsigned* ggen = g_ggen + g * 64;
        unsigned old = *ggen;
        __threadfence();
        if (atomicAdd(&g_gcnt[g * 64], 1u) == 7) {
            unsigned rold = *(volatile unsigned*)&g_rgen;
            if (atomicAdd(&g_rcnt, 1u) == 15) {
                g_rcnt = 0;
                __threadfence();
                atomicAdd(&g_rgen, 1u);
            } else {
                while (*(volatile unsigned*)&g_rgen == rold) { }
            }
            g_gcnt[g * 64] = 0;
            __threadfence();
            atomicAdd(&g_ggen[g * 64], 1u);
        } else {
            while (*ggen == old) { }
        }
        __threadfence();
    }
    __syncthreads();
}

// ---------------------------------------------------------------------------
// Persistent tensor-core GRU scan, v8 = R14 structure with:
//  (a) per-producer-CTA flag slots: producer tid0 st.release.gpu to its OWN
//      slot (no atomic serialization); consumer lanes 0..15 poll one slot
//      each (relaxed), then one fence.acq_rel.gpu.
//  (b) yh/yl (+ final y) stores moved AFTER the release — consumed only by
//      later kernels, kernel boundary orders them.
// ---------------------------------------------------------------------------
#define WS_BYTES  98304    // 2 splits * 64 ch * 24 rows * 16 elem * 2B
#define AB_BYTES  131072   // 2 splits * 64 ch * 32 b * 16 elem * 2B
#define SCAN_SMEM (WS_BYTES + AB_BYTES)   // 229376

__global__ __launch_bounds__(256, 1)
void gru_scan_mma(const float* __restrict__ gx, const float* __restrict__ Whh,
                  float* __restrict__ y,
                  __nv_bfloat16* __restrict__ yh, __nv_bfloat16* __restrict__ yl,
                  __nv_bfloat16* __restrict__ hbg, __nv_bfloat16* __restrict__ hlg,
                  unsigned* __restrict__ sflag)
{
    extern __shared__ char sm[];
    __nv_bfloat16* ws = (__nv_bfloat16*)sm;
    float* red = (float*)(sm + WS_BYTES);        // aliases A buffer (sync-protected)
    const uint32_t sb   = smem_u32(sm);
    const uint32_t WS_B = sb;
    const uint32_t AB_B = sb + WS_BYTES;

    const int tid  = threadIdx.x;
    const int wid  = tid >> 5;    // warp == group it loads & computes
    const int lane = tid & 31;
    const int cta  = blockIdx.x;
    const int eb   = tid >> 3;    // epilogue batch
    const int ejj  = tid & 7;     // epilogue col-in-cta
    const int ej   = cta * 8 + ejj;
    const int w8   = wid * 8;     // first chunk of this warp's group

    // ---- load + split Whh rows into SMEM (once), XOR-swizzled unpadded ----
    for (int i = tid; i < 24 * 1024; i += 256) {
        int r = i >> 10, k = i & 1023;
        int g = r >> 3, jj = r & 7;
        float v = Whh[((size_t)g * HID + cta * 8 + jj) * HID + k];
        __nv_bfloat16 h = __float2bfloat16(v);
        int e = k & 15;
        int off = (k >> 4) * 384 + r * 16 + (((e >> 3) ^ ((r >> 2) & 1)) * 8) + (e & 7);
        ws[off] = h;
        ws[24576 + off] = __float2bfloat16(v - __bfloat162float(h));
    }
    __syncthreads();

    // per-lane constant A offsets (byte) within a 1KB chunk, per m-half
    const uint32_t a_sw   = ((((lane >> 4) ^ (lane >> 2)) & 1) << 4);
    const uint32_t a_off0 = (uint32_t)(lane & 15) * 32 + a_sw;
    const uint32_t a_off1 = (uint32_t)(16 + (lane & 15)) * 32 + a_sw;

    // this warp consumes group `wid`: poll slot `lane` of that group (lanes 0..15)
    unsigned* pollslot = sflag + wid * 32 + (lane & 15);
    // this CTA produces into group (cta>>4), slot (cta&15)
    unsigned* myslot = sflag + (cta >> 4) * 32 + (cta & 15);

    float hprev = 0.f;

    for (int s = 0; s < SEQ; s++) {
        // gx prefetch into registers (independent of recurrence)
        const float* gp = gx + (size_t)s * (BATCH * G3) + (size_t)eb * G3 + cta * 8 + ejj;
        const float gxr = __ldg(gp);
        const float gxz = __ldg(gp + HID);
        const float gxn = __ldg(gp + 2 * HID);

        float gh0 = 0.f, gh1 = 0.f, gh2 = 0.f;

        if (s > 0) {
            const __nv_bfloat16* hb_rd = hbg + (size_t)((s & 1) ^ 1) * (64 * 512);
            const __nv_bfloat16* hl_rd = hlg + (size_t)((s & 1) ^ 1) * (64 * 512);

            // wait for all 16 producers of this warp's group: lane-parallel poll
            const unsigned target = (unsigned)s;
            if (lane < 16) {
                unsigned v;
                do {
                    asm volatile("ld.relaxed.gpu.global.u32 %0, [%1];"
                                 : "=r"(v) : "l"(pollslot) : "memory");
                } while (v < target);
            }
            __syncwarp();
            asm volatile("fence.acq_rel.gpu;" ::: "memory");   // acquire

            // commit group 1: hi slice (8 chunks x 1KB), 16 CP16/lane
#pragma unroll
            for (int it = 0; it < 16; it++) {
                int i = lane + it * 32;              // 0..511
                int chL = i >> 6;                    // 0..7
                int b = (i >> 1) & 31, half = i & 1;
                int ch = w8 + chL;
                const __nv_bfloat16* src = hb_rd + (size_t)ch * 512 + b * 16 + half * 8;
                uint32_t dst = AB_B + (uint32_t)ch * 1024 +
                               (uint32_t)b * 32 + (uint32_t)((half ^ ((b >> 2) & 1)) << 4);
                CP16(dst, src);
            }
            CP_COMMIT();
            // commit group 2: lo slice
#pragma unroll
            for (int it = 0; it < 16; it++) {
                int i = lane + it * 32;
                int chL = i >> 6;
                int b = (i >> 1) & 31, half = i & 1;
                int ch = w8 + chL;
                const __nv_bfloat16* src = hl_rd + (size_t)ch * 512 + b * 16 + half * 8;
                uint32_t dst = AB_B + 65536u + (uint32_t)ch * 1024 +
                               (uint32_t)b * 32 + (uint32_t)((half ^ ((b >> 2) & 1)) << 4);
                CP16(dst, src);
            }
            CP_COMMIT();

            float acc[2][3][4];
#pragma unroll
            for (int mi = 0; mi < 2; mi++)
#pragma unroll
                for (int t3 = 0; t3 < 3; t3++)
#pragma unroll
                    for (int v = 0; v < 4; v++) acc[mi][t3][v] = 0.f;

            // ---- phase 1: hi ready; Ah*Wh + Ah*Wl (lo slice still in flight) ----
            CP_WAIT1();
            __syncwarp();
#pragma unroll
            for (int i = 0; i < 8; i++) {
                const int ch = w8 + i;
                const uint32_t ab = AB_B + (uint32_t)ch * 1024;
                uint32_t aH0[4], aH1[4];
                LDSM_X4(aH0[0], aH0[1], aH0[2], aH0[3], ab + a_off0);
                LDSM_X4(aH1[0], aH1[1], aH1[2], aH1[3], ab + a_off1);
#pragma unroll
                for (int t3 = 0; t3 < 3; t3++) {
                    const int brow = t3 * 8 + (lane & 7);
                    const int bh = (lane >> 3) & 1;
                    uint32_t bH[2], bL[2];
                    const uint32_t bbase = WS_B + 2u * (ch * 384 + brow * 16 +
                                         ((bh ^ ((brow >> 2) & 1)) * 8));
                    LDSM_X2(bH[0], bH[1], bbase);
                    LDSM_X2(bL[0], bL[1], bbase + 2u * 24576);
                    MMA_BF16(acc[0][t3], aH0, bH);
                    MMA_BF16(acc[0][t3], aH0, bL);
                    MMA_BF16(acc[1][t3], aH1, bH);
                    MMA_BF16(acc[1][t3], aH1, bL);
                }
            }

            // ---- phase 2: lo ready; Al*Wh ----
            CP_WAIT0();
            __syncwarp();
#pragma unroll
            for (int i = 0; i < 8; i++) {
                const int ch = w8 + i;
                const uint32_t ab = AB_B + 65536u + (uint32_t)ch * 1024;
                uint32_t aL0[4], aL1[4];
                LDSM_X4(aL0[0], aL0[1], aL0[2], aL0[3], ab + a_off0);
                LDSM_X4(aL1[0], aL1[1], aL1[2], aL1[3], ab + a_off1);
#pragma unroll
                for (int t3 = 0; t3 < 3; t3++) {
                    const int brow = t3 * 8 + (lane & 7);
                    const int bh = (lane >> 3) & 1;
                    uint32_t bH[2];
                    const uint32_t bbase = WS_B + 2u * (ch * 384 + brow * 16 +
                                         ((bh ^ ((brow >> 2) & 1)) * 8));
                    LDSM_X2(bH[0], bH[1], bbase);
                    MMA_BF16(acc[0][t3], aL0, bH);
                    MMA_BF16(acc[1][t3], aL1, bH);
                }
            }
            __syncthreads();   // all warps done with A buffer -> red alias safe

            // cross-warp k reduction via SMEM: red[w][32 b][24 jj]
            const int qid = lane >> 2, qtr = lane & 3;
#pragma unroll
            for (int mi = 0; mi < 2; mi++)
#pragma unroll
                for (int t3 = 0; t3 < 3; t3++) {
                    float* rp = red + wid * 768 + (mi * 16 + qid) * 24 + t3 * 8 + qtr * 2;
                    *(float2*)rp = make_float2(acc[mi][t3][0], acc[mi][t3][1]);
                    *(float2*)(rp + 8 * 24) = make_float2(acc[mi][t3][2], acc[mi][t3][3]);
                }
            __syncthreads();

#pragma unroll
            for (int w2 = 0; w2 < 8; w2++) {
                const float* rp = red + w2 * 768 + eb * 24;
                gh0 += rp[ejj];
                gh1 += rp[8 + ejj];
                gh2 += rp[16 + ejj];
            }
        }

        // gate update for (b=eb, j=ej)
        const float r = 1.f / (1.f + __expf(-(gxr + gh0)));
        const float z = 1.f / (1.f + __expf(-(gxz + gh1)));
        const float npre = fmaf(r, gh2, gxn + gh2);
        const float e2 = __expf(2.f * npre);
        const float n = 1.f - 2.f / (e2 + 1.f);
        const float hnew = (1.f - z) * n + z * hprev;
        hprev = hnew;

        // CRITICAL PATH: only the h broadcast must precede the release
        const __nv_bfloat16 hh = __float2bfloat16(hnew);
        const __nv_bfloat16 hl = __float2bfloat16(hnew - __bfloat162float(hh));
        __nv_bfloat16* hb_wr = hbg + (size_t)(s & 1) * (64 * 512);
        __nv_bfloat16* hl_wr = hlg + (size_t)(s & 1) * (64 * 512);
        const int bidx = (ej >> 4) * 512 + eb * 16 + (ej & 15);
        hb_wr[bidx] = hh;
        hl_wr[bidx] = hl;

        // broadcast stores + red reads done -> release this CTA's slot
        __syncthreads();
        if (tid == 0) {
            asm volatile("st.release.gpu.global.u32 [%0], %1;"
                         :: "l"(myslot), "r"((unsigned)(s + 1)) : "memory");
        }

        // OFF critical path: GEMM A-splits + final fp32 h (consumed by later kernels)
        const size_t mrow = ((size_t)s * 32 + eb) * HID + ej;
        yh[mrow] = hh;
        yl[mrow] = hl;
        if (s == SEQ - 1)
            y[(size_t)eb * HID + ej] = hnew;
    }

    // reset flags for the next launch/replay (after everyone is done)
    grid_barrier();
    if (tid == 0)
        *(volatile unsigned*)myslot = 0u;
}

// ---------------------------------------------------------------------------
// Tail: new_hidden = stack([h_last0, h_last1])
// ---------------------------------------------------------------------------
__global__ void copy_tail(const float* __restrict__ h0,
                          const float* __restrict__ h1,
                          float* __restrict__ dst)
{
    int i = blockIdx.x * blockDim.x + threadIdx.x;
    dst[i]               = h0[i];
    dst[BATCH * HID + i] = h1[i];
}

// ---------------------------------------------------------------------------
// kernel_launch
// ---------------------------------------------------------------------------
extern "C" void kernel_launch(void* const* d_in, const int* in_sizes, int n_in,
                              void* d_out, int out_size)
{
    const float* x    = (const float*)d_in[0];
    const float* Wih0 = (const float*)d_in[1];
    const float* Whh0 = (const float*)d_in[2];
    const float* b0   = (const float*)d_in[3];
    const float* Wih1 = (const float*)d_in[4];
    const float* Whh1 = (const float*)d_in[5];
    const float* b1   = (const float*)d_in[6];
    const float* Wlin = (const float*)d_in[7];
    const float* blin = (const float*)d_in[8];
    float* out = (float*)d_out;

    float *gx, *y0, *y1;
    __nv_bfloat16 *ah, *al, *wh, *wl, *hb, *hl;
    unsigned *sf0, *sf1;
    cudaGetSymbolAddress((void**)&gx, g_gx);
    cudaGetSymbolAddress((void**)&y0, g_y0);
    cudaGetSymbolAddress((void**)&y1, g_y1);
    cudaGetSymbolAddress((void**)&ah, g_ah);
    cudaGetSymbolAddress((void**)&al, g_al);
    cudaGetSymbolAddress((void**)&wh, g_wh);
    cudaGetSymbolAddress((void**)&wl, g_wl);
    cudaGetSymbolAddress((void**)&hb, g_hb);
    cudaGetSymbolAddress((void**)&hl, g_hl);
    cudaGetSymbolAddress((void**)&sf0, g_sflag0);
    cudaGetSymbolAddress((void**)&sf1, g_sflag1);

    cudaFuncSetAttribute(gemm_mma, cudaFuncAttributeMaxDynamicSharedMemorySize, GEMM_SMEM);
    cudaFuncSetAttribute(gru_scan_mma, cudaFuncAttributeMaxDynamicSharedMemorySize, SCAN_SMEM);

    const int M = SEQ * BATCH;   // 16384

    // ---- layer 0 input GEMM: gx = x @ Wih0^T + b0 (time-major rows) ----
    conv_split<<<2048, 256>>>(x, IN_D, SEQ * IN_D, 9, (size_t)M * IN_D, ah, al);
    conv_split<<<2048, 256>>>(Wih0, 32 * IN_D, IN_D, 9, (size_t)G3 * IN_D, wh, wl);
    gemm_mma<<<dim3(G3 / 128, M / 128), 256, GEMM_SMEM>>>(
        ah, al, wh, wl, b0, gx, IN_D, 32 * G3, G3);

    // ---- layer-0 scan (y pointer = last-step slot only) ----
    gru_scan_mma<<<NCTA, 256, SCAN_SMEM>>>(gx, Whh0, y0, ah, al, hb, hl, sf0);

    // ---- layer 1 input GEMM: gx = y0 @ Wih1^T + b1 (A splits from scan) ----
    conv_split<<<2048, 256>>>(Wih1, 32 * HID, HID, 10, (size_t)G3 * HID, wh, wl);
    gemm_mma<<<dim3(G3 / 128, M / 128), 256, GEMM_SMEM>>>(
        ah, al, wh, wl, b1, gx, HID, 32 * G3, G3);

    // ---- layer-1 scan ----
    gru_scan_mma<<<NCTA, 256, SCAN_SMEM>>>(gx, Whh1, y1, ah, al, hb, hl, sf1);

    // ---- output GEMM: out[b][t][:] = y1 @ Wlin^T + blin ----
    conv_split<<<2048, 256>>>(Wlin, 32 * HID, HID, 10, (size_t)IN_D * HID, wh, wl);
    gemm_mma<<<dim3(IN_D / 128, M / 128), 256, GEMM_SMEM>>>(
        ah, al, wh, wl, blin, out, HID, IN_D, SEQ * IN_D);

    copy_tail<<<128, 256>>>(y0, y1, out + (size_t)BATCH * SEQ * IN_D);
}

// round 16
// speedup vs baseline: 1.5004x; 1.5004x over previous
#include <cuda_runtime.h>
#include <cuda_bf16.h>
#include <math.h>
#include <stdint.h>

// Problem constants
#define BATCH 32
#define SEQ   512
#define IN_D  512
#define HID   1024
#define G3    3072   // 3*HID
#define NCTA  128    // persistent scan grid size

typedef unsigned long long ull;

__device__ __forceinline__ uint32_t smem_u32(const void* p) {
    uint32_t a;
    asm("{ .reg .u64 t; cvta.to.shared.u64 t, %1; cvt.u32.u64 %0, t; }" : "=r"(a) : "l"(p));
    return a;
}

// mma.sync / ldmatrix / cp.async (baseline ISA, works on sm_103 target)
#define LDSM_X4(r0, r1, r2, r3, addr) \
    asm volatile("ldmatrix.sync.aligned.m8n8.x4.shared.b16 {%0,%1,%2,%3}, [%4];" \
        : "=r"(r0), "=r"(r1), "=r"(r2), "=r"(r3) : "r"(addr))
#define LDSM_X2(r0, r1, addr) \
    asm volatile("ldmatrix.sync.aligned.m8n8.x2.shared.b16 {%0,%1}, [%2];" \
        : "=r"(r0), "=r"(r1) : "r"(addr))
#define MMA_BF16(d, a, b) \
    asm volatile("mma.sync.aligned.m16n8k16.row.col.f32.bf16.bf16.f32 " \
        "{%0,%1,%2,%3}, {%4,%5,%6,%7}, {%8,%9}, {%0,%1,%2,%3};" \
        : "+f"((d)[0]), "+f"((d)[1]), "+f"((d)[2]), "+f"((d)[3]) \
        : "r"((a)[0]), "r"((a)[1]), "r"((a)[2]), "r"((a)[3]), "r"((b)[0]), "r"((b)[1]))
#define CP16(dst, src) \
    asm volatile("cp.async.cg.shared.global [%0], [%1], 16;" :: "r"(dst), "l"(src))
#define CP_COMMIT() asm volatile("cp.async.commit_group;" ::: "memory")
#define CP_WAIT0()  asm volatile("cp.async.wait_group 0;" ::: "memory")
#define CP_WAIT1()  asm volatile("cp.async.wait_group 1;" ::: "memory")

// ---------------------------------------------------------------------------
// Scratch (device globals)
// ---------------------------------------------------------------------------
__device__ float g_gx[(size_t)SEQ * BATCH * G3];
__device__ float g_y0[(size_t)SEQ * BATCH * HID];
__device__ float g_y1[(size_t)SEQ * BATCH * HID];
__device__ __nv_bfloat16 g_ah[(size_t)SEQ * BATCH * HID];  // A hi [M][K] row-major
__device__ __nv_bfloat16 g_al[(size_t)SEQ * BATCH * HID];  // A lo
__device__ __nv_bfloat16 g_wh[(size_t)G3 * HID];           // W hi [N][K] row-major
__device__ __nv_bfloat16 g_wl[(size_t)G3 * HID];           // W lo
__device__ __align__(16) __nv_bfloat16 g_hb[2][64 * 512];  // h hi, double-buffered, chunked [ch][b][16]
__device__ __align__(16) __nv_bfloat16 g_hl[2][64 * 512];  // h lo

// per-group producer progress flags (monotonic within a scan launch; reset at end)
__device__ unsigned g_sflag0[8 * 32];   // scan-0 flags, 128B apart
__device__ unsigned g_sflag1[8 * 32];   // scan-1 flags

// final-barrier state (used once per scan; gens monotonic, counts self-reset)
__device__ unsigned g_gcnt[16 * 64];
__device__ unsigned g_ggen[16 * 64];
__device__ unsigned g_rcnt;
__device__ unsigned g_rgen;

// ---------------------------------------------------------------------------
// fp32 -> (hi, lo) bf16 split.  Row m of src at (m>>5)*s0 + (m&31)*s1.
// ---------------------------------------------------------------------------
__global__ void conv_split(const float* __restrict__ src, int s0, int s1, int kbits,
                           size_t total, __nv_bfloat16* __restrict__ hi,
                           __nv_bfloat16* __restrict__ lo)
{
    const size_t km = ((size_t)1 << kbits) - 1;
    for (size_t idx = (size_t)blockIdx.x * blockDim.x + threadIdx.x; idx < total;
         idx += (size_t)gridDim.x * blockDim.x) {
        size_t m = idx >> kbits;
        int k = (int)(idx & km);
        float v = src[(m >> 5) * (size_t)s0 + (m & 31) * (size_t)s1 + k];
        __nv_bfloat16 h = __float2bfloat16(v);
        hi[idx] = h;
        lo[idx] = __float2bfloat16(v - __bfloat162float(h));
    }
}

// ---------------------------------------------------------------------------
// mma.sync split-bf16 GEMM (NT), 3-stage cp.async pipeline — unchanged R14
// ---------------------------------------------------------------------------
#define TPAD 40
#define TILE_BYTES (128 * TPAD * 2)
#define STAGE_BYTES (4 * TILE_BYTES)   // 40960
#define GEMM_SMEM (3 * STAGE_BYTES)    // 122880

__global__ __launch_bounds__(256)
void gemm_mma(const __nv_bfloat16* __restrict__ Ah, const __nv_bfloat16* __restrict__ Al,
              const __nv_bfloat16* __restrict__ Wh, const __nv_bfloat16* __restrict__ Wl,
              const float* __restrict__ bias, float* __restrict__ C,
              int K, int c_s0, int c_s1)
{
    extern __shared__ char smem[];
    const uint32_t sb = smem_u32(smem);

    const int tid  = threadIdx.x;
    const int wid  = tid >> 5;
    const int lane = tid & 31;
    const int wm   = wid >> 2;
    const int wn   = wid & 3;
    const int bm   = blockIdx.y * 128;
    const int bn   = blockIdx.x * 128;

    const __nv_bfloat16* srcs[4] = { Ah + (size_t)bm * K, Al + (size_t)bm * K,
                                     Wh + (size_t)bn * K, Wl + (size_t)bn * K };

    const int c0 = tid, c1 = tid + 256;
    const int r0 = c0 >> 2, q0 = c0 & 3;
    const int r1 = c1 >> 2, q1 = c1 & 3;

    float acc[4][4][4];
#pragma unroll
    for (int m = 0; m < 4; m++)
#pragma unroll
        for (int n = 0; n < 4; n++)
#pragma unroll
            for (int v = 0; v < 4; v++) acc[m][n][v] = 0.f;

    const int KT = K >> 5;

#pragma unroll
    for (int p = 0; p < 2; p++) {
        const uint32_t stg = sb + p * STAGE_BYTES;
        const int k0 = p << 5;
#pragma unroll
        for (int t = 0; t < 4; t++) {
            const uint32_t db = stg + t * TILE_BYTES;
            CP16(db + r0 * (TPAD * 2) + q0 * 16, srcs[t] + (size_t)r0 * K + k0 + q0 * 8);
            CP16(db + r1 * (TPAD * 2) + q1 * 16, srcs[t] + (size_t)r1 * K + k0 + q1 * 8);
        }
        CP_COMMIT();
    }

    const int a_row = (lane & 15);
    const int a_colh = (lane >> 4) * 8;
    const int b_row = (lane & 7);
    const int b_colh = ((lane >> 3) & 1) * 8;

    int bufi = 0;
    for (int kt = 0; kt < KT; kt++) {
        if (kt == KT - 1) { CP_WAIT0(); } else { CP_WAIT1(); }
        __syncthreads();

        const uint32_t buf = sb + bufi * STAGE_BYTES;

        if (kt + 2 < KT) {
            const int k0 = (kt + 2) << 5;
            int nb = bufi + 2; if (nb >= 3) nb -= 3;
            const uint32_t nbuf = sb + nb * STAGE_BYTES;
#pragma unroll
            for (int t = 0; t < 4; t++) {
                const uint32_t db = nbuf + t * TILE_BYTES;
                CP16(db + r0 * (TPAD * 2) + q0 * 16, srcs[t] + (size_t)r0 * K + k0 + q0 * 8);
                CP16(db + r1 * (TPAD * 2) + q1 * 16, srcs[t] + (size_t)r1 * K + k0 + q1 * 8);
            }
            CP_COMMIT();
        }

#pragma unroll
        for (int k16 = 0; k16 < 2; k16++) {
            uint32_t ah4[4][4], al4[4][4], bh2[4][2], bl2[4][2];
#pragma unroll
            for (int m = 0; m < 4; m++) {
                const uint32_t arow = wm * 64 + m * 16 + a_row;
                const uint32_t acol = k16 * 16 + a_colh;
                const uint32_t aoff = arow * (TPAD * 2) + acol * 2;
                LDSM_X4(ah4[m][0], ah4[m][1], ah4[m][2], ah4[m][3], buf + 0 * TILE_BYTES + aoff);
                LDSM_X4(al4[m][0], al4[m][1], al4[m][2], al4[m][3], buf + 1 * TILE_BYTES + aoff);
            }
#pragma unroll
            for (int n = 0; n < 4; n++) {
                const uint32_t brow = wn * 32 + n * 8 + b_row;
                const uint32_t bcol = k16 * 16 + b_colh;
                const uint32_t boff = brow * (TPAD * 2) + bcol * 2;
                LDSM_X2(bh2[n][0], bh2[n][1], buf + 2 * TILE_BYTES + boff);
                LDSM_X2(bl2[n][0], bl2[n][1], buf + 3 * TILE_BYTES + boff);
            }
#pragma unroll
            for (int m = 0; m < 4; m++)
#pragma unroll
                for (int n = 0; n < 4; n++) {
                    MMA_BF16(acc[m][n], ah4[m], bh2[n]);
                    MMA_BF16(acc[m][n], ah4[m], bl2[n]);
                    MMA_BF16(acc[m][n], al4[m], bh2[n]);
                }
        }
        if (++bufi >= 3) bufi = 0;
    }

    const int qid = lane >> 2;
    const int qtr = lane & 3;
#pragma unroll
    for (int m = 0; m < 4; m++) {
        const int ra = bm + wm * 64 + m * 16 + qid;
        const int rb = ra + 8;
        float* crowa = C + (size_t)(ra >> 5) * c_s0 + (size_t)(ra & 31) * c_s1;
        float* crowb = C + (size_t)(rb >> 5) * c_s0 + (size_t)(rb & 31) * c_s1;
#pragma unroll
        for (int n = 0; n < 4; n++) {
            const int col = bn + wn * 32 + n * 8 + qtr * 2;
            const float bv0 = bias[col], bv1 = bias[col + 1];
            float2 va, vb;
            va.x = acc[m][n][0] + bv0; va.y = acc[m][n][1] + bv1;
            vb.x = acc[m][n][2] + bv0; vb.y = acc[m][n][3] + bv1;
            *(float2*)(crowa + col) = va;
            *(float2*)(crowb + col) = vb;
        }
    }
}

// ---------------------------------------------------------------------------
// grid-wide barrier — two-level tree. Used ONCE per scan (flag reset).
// ---------------------------------------------------------------------------
__device__ __forceinline__ void grid_barrier()
{
    __syncthreads();
    if (threadIdx.x == 0) {
        const int g = blockIdx.x >> 3;
        volatile unsigned* ggen = g_ggen + g * 64;
        unsigned old = *ggen;
        __threadfence();
        if (atomicAdd(&g_gcnt[g * 64], 1u) == 7) {
            unsigned rold = *(volatile unsigned*)&g_rgen;
            if (atomicAdd(&g_rcnt, 1u) == 15) {
                g_rcnt = 0;
                __threadfence();
                atomicAdd(&g_rgen, 1u);
            } else {
                while (*(volatile unsigned*)&g_rgen == rold) { }
            }
            g_gcnt[g * 64] = 0;
            __threadfence();
            atomicAdd(&g_ggen[g * 64], 1u);
        } else {
            while (*ggen == old) { }
        }
        __threadfence();
    }
    __syncthreads();
}

// ---------------------------------------------------------------------------
// Persistent tensor-core GRU scan — R14 protocol EXACTLY (aggregate group
// counter via red.release.gpu.add, lane-0 ld.acquire poll), with one change:
// yh/yl (+ final fp32 y) stores moved AFTER the release. They are consumed
// only by subsequent kernel launches (kernel-boundary ordering), so they
// come off the store->release critical path.
// ---------------------------------------------------------------------------
#define WS_BYTES  98304    // 2 splits * 64 ch * 24 rows * 16 elem * 2B
#define AB_BYTES  131072   // 2 splits * 64 ch * 32 b * 16 elem * 2B
#define SCAN_SMEM (WS_BYTES + AB_BYTES)   // 229376

__global__ __launch_bounds__(256, 1)
void gru_scan_mma(const float* __restrict__ gx, const float* __restrict__ Whh,
                  float* __restrict__ y,
                  __nv_bfloat16* __restrict__ yh, __nv_bfloat16* __restrict__ yl,
                  __nv_bfloat16* __restrict__ hbg, __nv_bfloat16* __restrict__ hlg,
                  unsigned* __restrict__ sflag)
{
    extern __shared__ char sm[];
    __nv_bfloat16* ws = (__nv_bfloat16*)sm;
    float* red = (float*)(sm + WS_BYTES);        // aliases A buffer (sync-protected)
    const uint32_t sb   = smem_u32(sm);
    const uint32_t WS_B = sb;
    const uint32_t AB_B = sb + WS_BYTES;

    const int tid  = threadIdx.x;
    const int wid  = tid >> 5;    // warp == group it loads & computes
    const int lane = tid & 31;
    const int cta  = blockIdx.x;
    const int eb   = tid >> 3;    // epilogue batch
    const int ejj  = tid & 7;     // epilogue col-in-cta
    const int ej   = cta * 8 + ejj;
    const int w8   = wid * 8;     // first chunk of this warp's group

    // ---- load + split Whh rows into SMEM (once), XOR-swizzled unpadded ----
    for (int i = tid; i < 24 * 1024; i += 256) {
        int r = i >> 10, k = i & 1023;
        int g = r >> 3, jj = r & 7;
        float v = Whh[((size_t)g * HID + cta * 8 + jj) * HID + k];
        __nv_bfloat16 h = __float2bfloat16(v);
        int e = k & 15;
        int off = (k >> 4) * 384 + r * 16 + (((e >> 3) ^ ((r >> 2) & 1)) * 8) + (e & 7);
        ws[off] = h;
        ws[24576 + off] = __float2bfloat16(v - __bfloat162float(h));
    }
    __syncthreads();

    // per-lane constant A offsets (byte) within a 1KB chunk, per m-half
    const uint32_t a_sw   = ((((lane >> 4) ^ (lane >> 2)) & 1) << 4);
    const uint32_t a_off0 = (uint32_t)(lane & 15) * 32 + a_sw;
    const uint32_t a_off1 = (uint32_t)(16 + (lane & 15)) * 32 + a_sw;

    unsigned* myflag = sflag + wid * 32;
    unsigned* grpflag = sflag + (cta >> 4) * 32;

    float hprev = 0.f;

    for (int s = 0; s < SEQ; s++) {
        // gx prefetch into registers (independent of recurrence)
        const float* gp = gx + (size_t)s * (BATCH * G3) + (size_t)eb * G3 + cta * 8 + ejj;
        const float gxr = __ldg(gp);
        const float gxz = __ldg(gp + HID);
        const float gxn = __ldg(gp + 2 * HID);

        float gh0 = 0.f, gh1 = 0.f, gh2 = 0.f;

        if (s > 0) {
            const __nv_bfloat16* hb_rd = hbg + (size_t)((s & 1) ^ 1) * (64 * 512);
            const __nv_bfloat16* hl_rd = hlg + (size_t)((s & 1) ^ 1) * (64 * 512);

            // wait (acquire) for this warp's group producers to finish step s-1
            const unsigned target = 16u * (unsigned)s;
            if (lane == 0) {
                unsigned v;
                do {
                    asm volatile("ld.acquire.gpu.global.u32 %0, [%1];"
                                 : "=r"(v) : "l"(myflag) : "memory");
                } while (v < target);
            }
            __syncwarp();

            // commit group 1: hi slice (8 chunks x 1KB), 16 CP16/lane
#pragma unroll
            for (int it = 0; it < 16; it++) {
                int i = lane + it * 32;              // 0..511
                int chL = i >> 6;                    // 0..7
                int b = (i >> 1) & 31, half = i & 1;
                int ch = w8 + chL;
                const __nv_bfloat16* src = hb_rd + (size_t)ch * 512 + b * 16 + half * 8;
                uint32_t dst = AB_B + (uint32_t)ch * 1024 +
                               (uint32_t)b * 32 + (uint32_t)((half ^ ((b >> 2) & 1)) << 4);
                CP16(dst, src);
            }
            CP_COMMIT();
            // commit group 2: lo slice
#pragma unroll
            for (int it = 0; it < 16; it++) {
                int i = lane + it * 32;
                int chL = i >> 6;
                int b = (i >> 1) & 31, half = i & 1;
                int ch = w8 + chL;
                const __nv_bfloat16* src = hl_rd + (size_t)ch * 512 + b * 16 + half * 8;
                uint32_t dst = AB_B + 65536u + (uint32_t)ch * 1024 +
                               (uint32_t)b * 32 + (uint32_t)((half ^ ((b >> 2) & 1)) << 4);
                CP16(dst, src);
            }
            CP_COMMIT();

            float acc[2][3][4];
#pragma unroll
            for (int mi = 0; mi < 2; mi++)
#pragma unroll
                for (int t3 = 0; t3 < 3; t3++)
#pragma unroll
                    for (int v = 0; v < 4; v++) acc[mi][t3][v] = 0.f;

            // ---- phase 1: hi ready; Ah*Wh + Ah*Wl (lo slice still in flight) ----
            CP_WAIT1();
            __syncwarp();
#pragma unroll
            for (int i = 0; i < 8; i++) {
                const int ch = w8 + i;
                const uint32_t ab = AB_B + (uint32_t)ch * 1024;
                uint32_t aH0[4], aH1[4];
                LDSM_X4(aH0[0], aH0[1], aH0[2], aH0[3], ab + a_off0);
                LDSM_X4(aH1[0], aH1[1], aH1[2], aH1[3], ab + a_off1);
#pragma unroll
                for (int t3 = 0; t3 < 3; t3++) {
                    const int brow = t3 * 8 + (lane & 7);
                    const int bh = (lane >> 3) & 1;
                    uint32_t bH[2], bL[2];
                    const uint32_t bbase = WS_B + 2u * (ch * 384 + brow * 16 +
                                         ((bh ^ ((brow >> 2) & 1)) * 8));
                    LDSM_X2(bH[0], bH[1], bbase);
                    LDSM_X2(bL[0], bL[1], bbase + 2u * 24576);
                    MMA_BF16(acc[0][t3], aH0, bH);
                    MMA_BF16(acc[0][t3], aH0, bL);
                    MMA_BF16(acc[1][t3], aH1, bH);
                    MMA_BF16(acc[1][t3], aH1, bL);
                }
            }

            // ---- phase 2: lo ready; Al*Wh ----
            CP_WAIT0();
            __syncwarp();
#pragma unroll
            for (int i = 0; i < 8; i++) {
                const int ch = w8 + i;
                const uint32_t ab = AB_B + 65536u + (uint32_t)ch * 1024;
                uint32_t aL0[4], aL1[4];
                LDSM_X4(aL0[0], aL0[1], aL0[2], aL0[3], ab + a_off0);
                LDSM_X4(aL1[0], aL1[1], aL1[2], aL1[3], ab + a_off1);
#pragma unroll
                for (int t3 = 0; t3 < 3; t3++) {
                    const int brow = t3 * 8 + (lane & 7);
                    const int bh = (lane >> 3) & 1;
                    uint32_t bH[2];
                    const uint32_t bbase = WS_B + 2u * (ch * 384 + brow * 16 +
                                         ((bh ^ ((brow >> 2) & 1)) * 8));
                    LDSM_X2(bH[0], bH[1], bbase);
                    MMA_BF16(acc[0][t3], aL0, bH);
                    MMA_BF16(acc[1][t3], aL1, bH);
                }
            }
            __syncthreads();   // all warps done with A buffer -> red alias safe

            // cross-warp k reduction via SMEM: red[w][32 b][24 jj]
            const int qid = lane >> 2, qtr = lane & 3;
#pragma unroll
            for (int mi = 0; mi < 2; mi++)
#pragma unroll
                for (int t3 = 0; t3 < 3; t3++) {
                    float* rp = red + wid * 768 + (mi * 16 + qid) * 24 + t3 * 8 + qtr * 2;
                    *(float2*)rp = make_float2(acc[mi][t3][0], acc[mi][t3][1]);
                    *(float2*)(rp + 8 * 24) = make_float2(acc[mi][t3][2], acc[mi][t3][3]);
                }
            __syncthreads();

#pragma unroll
            for (int w2 = 0; w2 < 8; w2++) {
                const float* rp = red + w2 * 768 + eb * 24;
                gh0 += rp[ejj];
                gh1 += rp[8 + ejj];
                gh2 += rp[16 + ejj];
            }
        }

        // gate update for (b=eb, j=ej)
        const float r = 1.f / (1.f + __expf(-(gxr + gh0)));
        const float z = 1.f / (1.f + __expf(-(gxz + gh1)));
        const float npre = fmaf(r, gh2, gxn + gh2);
        const float e2 = __expf(2.f * npre);
        const float n = 1.f - 2.f / (e2 + 1.f);
        const float hnew = (1.f - z) * n + z * hprev;
        hprev = hnew;

        // CRITICAL PATH: only the h broadcast must precede the release
        const __nv_bfloat16 hh = __float2bfloat16(hnew);
        const __nv_bfloat16 hl = __float2bfloat16(hnew - __bfloat162float(hh));
        __nv_bfloat16* hb_wr = hbg + (size_t)(s & 1) * (64 * 512);
        __nv_bfloat16* hl_wr = hlg + (size_t)(s & 1) * (64 * 512);
        const int bidx = (ej >> 4) * 512 + eb * 16 + (ej & 15);
        hb_wr[bidx] = hh;
        hl_wr[bidx] = hl;

        // broadcast stores + red reads done -> release group progress (R14 scheme)
        __syncthreads();
        if (tid == 0) {
            asm volatile("red.release.gpu.global.add.u32 [%0], 1;"
                         :: "l"(grpflag) : "memory");
        }

        // OFF critical path: GEMM A-splits + final fp32 h (consumed by later kernels)
        const size_t mrow = ((size_t)s * 32 + eb) * HID + ej;
        yh[mrow] = hh;
        yl[mrow] = hl;
        if (s == SEQ - 1)
            y[(size_t)eb * HID + ej] = hnew;
    }

    // reset flags for the next launch/replay (after everyone is done)
    grid_barrier();
    if (tid == 0 && cta < 8)
        *(volatile unsigned*)(sflag + cta * 32) = 0u;
}

// ---------------------------------------------------------------------------
// Tail: new_hidden = stack([h_last0, h_last1])
// ---------------------------------------------------------------------------
__global__ void copy_tail(const float* __restrict__ h0,
                          const float* __restrict__ h1,
                          float* __restrict__ dst)
{
    int i = blockIdx.x * blockDim.x + threadIdx.x;
    dst[i]               = h0[i];
    dst[BATCH * HID + i] = h1[i];
}

// ---------------------------------------------------------------------------
// kernel_launch
// ---------------------------------------------------------------------------
extern "C" void kernel_launch(void* const* d_in, const int* in_sizes, int n_in,
                              void* d_out, int out_size)
{
    const float* x    = (const float*)d_in[0];
    const float* Wih0 = (const float*)d_in[1];
    const float* Whh0 = (const float*)d_in[2];
    const float* b0   = (const float*)d_in[3];
    const float* Wih1 = (const float*)d_in[4];
    const float* Whh1 = (const float*)d_in[5];
    const float* b1   = (const float*)d_in[6];
    const float* Wlin = (const float*)d_in[7];
    const float* blin = (const float*)d_in[8];
    float* out = (float*)d_out;

    float *gx, *y0, *y1;
    __nv_bfloat16 *ah, *al, *wh, *wl, *hb, *hl;
    unsigned *sf0, *sf1;
    cudaGetSymbolAddress((void**)&gx, g_gx);
    cudaGetSymbolAddress((void**)&y0, g_y0);
    cudaGetSymbolAddress((void**)&y1, g_y1);
    cudaGetSymbolAddress((void**)&ah, g_ah);
    cudaGetSymbolAddress((void**)&al, g_al);
    cudaGetSymbolAddress((void**)&wh, g_wh);
    cudaGetSymbolAddress((void**)&wl, g_wl);
    cudaGetSymbolAddress((void**)&hb, g_hb);
    cudaGetSymbolAddress((void**)&hl, g_hl);
    cudaGetSymbolAddress((void**)&sf0, g_sflag0);
    cudaGetSymbolAddress((void**)&sf1, g_sflag1);

    cudaFuncSetAttribute(gemm_mma, cudaFuncAttributeMaxDynamicSharedMemorySize, GEMM_SMEM);
    cudaFuncSetAttribute(gru_scan_mma, cudaFuncAttributeMaxDynamicSharedMemorySize, SCAN_SMEM);

    const int M = SEQ * BATCH;   // 16384

    // ---- layer 0 input GEMM: gx = x @ Wih0^T + b0 (time-major rows) ----
    conv_split<<<2048, 256>>>(x, IN_D, SEQ * IN_D, 9, (size_t)M * IN_D, ah, al);
    conv_split<<<2048, 256>>>(Wih0, 32 * IN_D, IN_D, 9, (size_t)G3 * IN_D, wh, wl);
    gemm_mma<<<dim3(G3 / 128, M / 128), 256, GEMM_SMEM>>>(
        ah, al, wh, wl, b0, gx, IN_D, 32 * G3, G3);

    // ---- layer-0 scan (y pointer = last-step slot only) ----
    gru_scan_mma<<<NCTA, 256, SCAN_SMEM>>>(gx, Whh0, y0, ah, al, hb, hl, sf0);

    // ---- layer 1 input GEMM: gx = y0 @ Wih1^T + b1 (A splits from scan) ----
    conv_split<<<2048, 256>>>(Wih1, 32 * HID, HID, 10, (size_t)G3 * HID, wh, wl);
    gemm_mma<<<dim3(G3 / 128, M / 128), 256, GEMM_SMEM>>>(
        ah, al, wh, wl, b1, gx, HID, 32 * G3, G3);

    // ---- layer-1 scan ----
    gru_scan_mma<<<NCTA, 256, SCAN_SMEM>>>(gx, Whh1, y1, ah, al, hb, hl, sf1);

    // ---- output GEMM: out[b][t][:] = y1 @ Wlin^T + blin ----
    conv_split<<<2048, 256>>>(Wlin, 32 * HID, HID, 10, (size_t)IN_D * HID, wh, wl);
    gemm_mma<<<dim3(IN_D / 128, M / 128), 256, GEMM_SMEM>>>(
        ah, al, wh, wl, blin, out, HID, IN_D, SEQ * IN_D);

    copy_tail<<<128, 256>>>(y0, y1, out + (size_t)BATCH * SEQ * IN_D);
}

// round 17
// speedup vs baseline: 1.5784x; 1.0520x over previous
#include <cuda_runtime.h>
#include <cuda_bf16.h>
#include <math.h>
#include <stdint.h>

// Problem constants
#define BATCH 32
#define SEQ   512
#define IN_D  512
#define HID   1024
#define G3    3072   // 3*HID
#define NCTA  128    // persistent scan grid size

typedef unsigned long long ull;

__device__ __forceinline__ uint32_t smem_u32(const void* p) {
    uint32_t a;
    asm("{ .reg .u64 t; cvta.to.shared.u64 t, %1; cvt.u32.u64 %0, t; }" : "=r"(a) : "l"(p));
    return a;
}

// mma.sync / ldmatrix / cp.async (baseline ISA, works on sm_103 target)
#define LDSM_X4(r0, r1, r2, r3, addr) \
    asm volatile("ldmatrix.sync.aligned.m8n8.x4.shared.b16 {%0,%1,%2,%3}, [%4];" \
        : "=r"(r0), "=r"(r1), "=r"(r2), "=r"(r3) : "r"(addr))
#define LDSM_X2(r0, r1, addr) \
    asm volatile("ldmatrix.sync.aligned.m8n8.x2.shared.b16 {%0,%1}, [%2];" \
        : "=r"(r0), "=r"(r1) : "r"(addr))
#define MMA_BF16(d, a, b) \
    asm volatile("mma.sync.aligned.m16n8k16.row.col.f32.bf16.bf16.f32 " \
        "{%0,%1,%2,%3}, {%4,%5,%6,%7}, {%8,%9}, {%0,%1,%2,%3};" \
        : "+f"((d)[0]), "+f"((d)[1]), "+f"((d)[2]), "+f"((d)[3]) \
        : "r"((a)[0]), "r"((a)[1]), "r"((a)[2]), "r"((a)[3]), "r"((b)[0]), "r"((b)[1]))
#define CP16(dst, src) \
    asm volatile("cp.async.cg.shared.global [%0], [%1], 16;" :: "r"(dst), "l"(src))
#define CP_COMMIT() asm volatile("cp.async.commit_group;" ::: "memory")
#define CP_WAIT0()  asm volatile("cp.async.wait_group 0;" ::: "memory")
#define CP_WAIT1()  asm volatile("cp.async.wait_group 1;" ::: "memory")

// ---------------------------------------------------------------------------
// Scratch (device globals)
// ---------------------------------------------------------------------------
__device__ float g_gx[(size_t)SEQ * BATCH * G3];
__device__ float g_y0[(size_t)SEQ * BATCH * HID];
__device__ float g_y1[(size_t)SEQ * BATCH * HID];
__device__ __nv_bfloat16 g_ah[(size_t)SEQ * BATCH * HID];  // A hi [M][K] row-major
__device__ __nv_bfloat16 g_al[(size_t)SEQ * BATCH * HID];  // A lo
__device__ __nv_bfloat16 g_wh[(size_t)G3 * HID];           // W hi [N][K] row-major
__device__ __nv_bfloat16 g_wl[(size_t)G3 * HID];           // W lo
__device__ __align__(16) __nv_bfloat16 g_hb[2][64 * 512];  // h hi, double-buffered, chunked [ch][b][16]
__device__ __align__(16) __nv_bfloat16 g_hl[2][64 * 512];  // h lo

// per-group producer progress flags (monotonic within a scan launch; reset at end)
__device__ unsigned g_sflag0[8 * 32];   // scan-0 flags, 128B apart
__device__ unsigned g_sflag1[8 * 32];   // scan-1 flags

// final-barrier state (used once per scan; gens monotonic, counts self-reset)
__device__ unsigned g_gcnt[16 * 64];
__device__ unsigned g_ggen[16 * 64];
__device__ unsigned g_rcnt;
__device__ unsigned g_rgen;

// ---------------------------------------------------------------------------
// fp32 -> (hi, lo) bf16 split.  Row m of src at (m>>5)*s0 + (m&31)*s1.
// ---------------------------------------------------------------------------
__global__ void conv_split(const float* __restrict__ src, int s0, int s1, int kbits,
                           size_t total, __nv_bfloat16* __restrict__ hi,
                           __nv_bfloat16* __restrict__ lo)
{
    const size_t km = ((size_t)1 << kbits) - 1;
    for (size_t idx = (size_t)blockIdx.x * blockDim.x + threadIdx.x; idx < total;
         idx += (size_t)gridDim.x * blockDim.x) {
        size_t m = idx >> kbits;
        int k = (int)(idx & km);
        float v = src[(m >> 5) * (size_t)s0 + (m & 31) * (size_t)s1 + k];
        __nv_bfloat16 h = __float2bfloat16(v);
        hi[idx] = h;
        lo[idx] = __float2bfloat16(v - __bfloat162float(h));
    }
}

// ---------------------------------------------------------------------------
// mma.sync split-bf16 GEMM (NT), v3: 2-stage cp.async pipeline at 2 CTAs/SM
// (81920B smem), single __syncthreads per k-iter. Latency hidden by
// occupancy instead of pipeline depth.
// ---------------------------------------------------------------------------
#define TPAD 40
#define TILE_BYTES (128 * TPAD * 2)
#define STAGE_BYTES (4 * TILE_BYTES)   // 40960
#define GEMM_SMEM (2 * STAGE_BYTES)    // 81920 -> 2 CTAs/SM

__global__ __launch_bounds__(256, 2)
void gemm_mma(const __nv_bfloat16* __restrict__ Ah, const __nv_bfloat16* __restrict__ Al,
              const __nv_bfloat16* __restrict__ Wh, const __nv_bfloat16* __restrict__ Wl,
              const float* __restrict__ bias, float* __restrict__ C,
              int K, int c_s0, int c_s1)
{
    extern __shared__ char smem[];
    const uint32_t sb = smem_u32(smem);

    const int tid  = threadIdx.x;
    const int wid  = tid >> 5;
    const int lane = tid & 31;
    const int wm   = wid >> 2;
    const int wn   = wid & 3;
    const int bm   = blockIdx.y * 128;
    const int bn   = blockIdx.x * 128;

    const __nv_bfloat16* srcs[4] = { Ah + (size_t)bm * K, Al + (size_t)bm * K,
                                     Wh + (size_t)bn * K, Wl + (size_t)bn * K };

    const int c0 = tid, c1 = tid + 256;
    const int r0 = c0 >> 2, q0 = c0 & 3;
    const int r1 = c1 >> 2, q1 = c1 & 3;

    float acc[4][4][4];
#pragma unroll
    for (int m = 0; m < 4; m++)
#pragma unroll
        for (int n = 0; n < 4; n++)
#pragma unroll
            for (int v = 0; v < 4; v++) acc[m][n][v] = 0.f;

    const int KT = K >> 5;

    // prologue: stage for kt=0
    {
        const uint32_t stg = sb;
#pragma unroll
        for (int t = 0; t < 4; t++) {
            const uint32_t db = stg + t * TILE_BYTES;
            CP16(db + r0 * (TPAD * 2) + q0 * 16, srcs[t] + (size_t)r0 * K + q0 * 8);
            CP16(db + r1 * (TPAD * 2) + q1 * 16, srcs[t] + (size_t)r1 * K + q1 * 8);
        }
        CP_COMMIT();
    }

    const int a_row = (lane & 15);
    const int a_colh = (lane >> 4) * 8;
    const int b_row = (lane & 7);
    const int b_colh = ((lane >> 3) & 1) * 8;

    for (int kt = 0; kt < KT; kt++) {
        CP_WAIT0();
        __syncthreads();   // stage kt visible; everyone done computing kt-1

        const uint32_t buf = sb + (kt & 1) * STAGE_BYTES;

        if (kt + 1 < KT) {
            const int k0 = (kt + 1) << 5;
            const uint32_t nbuf = sb + ((kt + 1) & 1) * STAGE_BYTES;
#pragma unroll
            for (int t = 0; t < 4; t++) {
                const uint32_t db = nbuf + t * TILE_BYTES;
                CP16(db + r0 * (TPAD * 2) + q0 * 16, srcs[t] + (size_t)r0 * K + k0 + q0 * 8);
                CP16(db + r1 * (TPAD * 2) + q1 * 16, srcs[t] + (size_t)r1 * K + k0 + q1 * 8);
            }
            CP_COMMIT();
        }

#pragma unroll
        for (int k16 = 0; k16 < 2; k16++) {
            uint32_t ah4[4][4], al4[4][4], bh2[4][2], bl2[4][2];
#pragma unroll
            for (int m = 0; m < 4; m++) {
                const uint32_t arow = wm * 64 + m * 16 + a_row;
                const uint32_t acol = k16 * 16 + a_colh;
                const uint32_t aoff = arow * (TPAD * 2) + acol * 2;
                LDSM_X4(ah4[m][0], ah4[m][1], ah4[m][2], ah4[m][3], buf + 0 * TILE_BYTES + aoff);
                LDSM_X4(al4[m][0], al4[m][1], al4[m][2], al4[m][3], buf + 1 * TILE_BYTES + aoff);
            }
#pragma unroll
            for (int n = 0; n < 4; n++) {
                const uint32_t brow = wn * 32 + n * 8 + b_row;
                const uint32_t bcol = k16 * 16 + b_colh;
                const uint32_t boff = brow * (TPAD * 2) + bcol * 2;
                LDSM_X2(bh2[n][0], bh2[n][1], buf + 2 * TILE_BYTES + boff);
                LDSM_X2(bl2[n][0], bl2[n][1], buf + 3 * TILE_BYTES + boff);
            }
#pragma unroll
            for (int m = 0; m < 4; m++)
#pragma unroll
                for (int n = 0; n < 4; n++) {
                    MMA_BF16(acc[m][n], ah4[m], bh2[n]);
                    MMA_BF16(acc[m][n], ah4[m], bl2[n]);
                    MMA_BF16(acc[m][n], al4[m], bh2[n]);
                }
        }
    }

    const int qid = lane >> 2;
    const int qtr = lane & 3;
#pragma unroll
    for (int m = 0; m < 4; m++) {
        const int ra = bm + wm * 64 + m * 16 + qid;
        const int rb = ra + 8;
        float* crowa = C + (size_t)(ra >> 5) * c_s0 + (size_t)(ra & 31) * c_s1;
        float* crowb = C + (size_t)(rb >> 5) * c_s0 + (size_t)(rb & 31) * c_s1;
#pragma unroll
        for (int n = 0; n < 4; n++) {
            const int col = bn + wn * 32 + n * 8 + qtr * 2;
            const float bv0 = bias[col], bv1 = bias[col + 1];
            float2 va, vb;
            va.x = acc[m][n][0] + bv0; va.y = acc[m][n][1] + bv1;
            vb.x = acc[m][n][2] + bv0; vb.y = acc[m][n][3] + bv1;
            *(float2*)(crowa + col) = va;
            *(float2*)(crowb + col) = vb;
        }
    }
}

// ---------------------------------------------------------------------------
// grid-wide barrier — two-level tree. Used ONCE per scan (flag reset).
// ---------------------------------------------------------------------------
__device__ __forceinline__ void grid_barrier()
{
    __syncthreads();
    if (threadIdx.x == 0) {
        const int g = blockIdx.x >> 3;
        volatile unsigned* ggen = g_ggen + g * 64;
        unsigned old = *ggen;
        __threadfence();
        if (atomicAdd(&g_gcnt[g * 64], 1u) == 7) {
            unsigned rold = *(volatile unsigned*)&g_rgen;
            if (atomicAdd(&g_rcnt, 1u) == 15) {
                g_rcnt = 0;
                __threadfence();
                atomicAdd(&g_rgen, 1u);
            } else {
                while (*(volatile unsigned*)&g_rgen == rold) { }
            }
            g_gcnt[g * 64] = 0;
            __threadfence();
            atomicAdd(&g_ggen[g * 64], 1u);
        } else {
            while (*ggen == old) { }
        }
        __threadfence();
    }
    __syncthreads();
}

// ---------------------------------------------------------------------------
// Persistent tensor-core GRU scan — R16 EXACTLY (best passing config):
// R14 flag protocol + post-release history stores.
// ---------------------------------------------------------------------------
#define WS_BYTES  98304    // 2 splits * 64 ch * 24 rows * 16 elem * 2B
#define AB_BYTES  131072   // 2 splits * 64 ch * 32 b * 16 elem * 2B
#define SCAN_SMEM (WS_BYTES + AB_BYTES)   // 229376

__global__ __launch_bounds__(256, 1)
void gru_scan_mma(const float* __restrict__ gx, const float* __restrict__ Whh,
                  float* __restrict__ y,
                  __nv_bfloat16* __restrict__ yh, __nv_bfloat16* __restrict__ yl,
                  __nv_bfloat16* __restrict__ hbg, __nv_bfloat16* __restrict__ hlg,
                  unsigned* __restrict__ sflag)
{
    extern __shared__ char sm[];
    __nv_bfloat16* ws = (__nv_bfloat16*)sm;
    float* red = (float*)(sm + WS_BYTES);        // aliases A buffer (sync-protected)
    const uint32_t sb   = smem_u32(sm);
    const uint32_t WS_B = sb;
    const uint32_t AB_B = sb + WS_BYTES;

    const int tid  = threadIdx.x;
    const int wid  = tid >> 5;    // warp == group it loads & computes
    const int lane = tid & 31;
    const int cta  = blockIdx.x;
    const int eb   = tid >> 3;    // epilogue batch
    const int ejj  = tid & 7;     // epilogue col-in-cta
    const int ej   = cta * 8 + ejj;
    const int w8   = wid * 8;     // first chunk of this warp's group

    // ---- load + split Whh rows into SMEM (once), XOR-swizzled unpadded ----
    for (int i = tid; i < 24 * 1024; i += 256) {
        int r = i >> 10, k = i & 1023;
        int g = r >> 3, jj = r & 7;
        float v = Whh[((size_t)g * HID + cta * 8 + jj) * HID + k];
        __nv_bfloat16 h = __float2bfloat16(v);
        int e = k & 15;
        int off = (k >> 4) * 384 + r * 16 + (((e >> 3) ^ ((r >> 2) & 1)) * 8) + (e & 7);
        ws[off] = h;
        ws[24576 + off] = __float2bfloat16(v - __bfloat162float(h));
    }
    __syncthreads();

    // per-lane constant A offsets (byte) within a 1KB chunk, per m-half
    const uint32_t a_sw   = ((((lane >> 4) ^ (lane >> 2)) & 1) << 4);
    const uint32_t a_off0 = (uint32_t)(lane & 15) * 32 + a_sw;
    const uint32_t a_off1 = (uint32_t)(16 + (lane & 15)) * 32 + a_sw;

    unsigned* myflag = sflag + wid * 32;
    unsigned* grpflag = sflag + (cta >> 4) * 32;

    float hprev = 0.f;

    for (int s = 0; s < SEQ; s++) {
        // gx prefetch into registers (independent of recurrence)
        const float* gp = gx + (size_t)s * (BATCH * G3) + (size_t)eb * G3 + cta * 8 + ejj;
        const float gxr = __ldg(gp);
        const float gxz = __ldg(gp + HID);
        const float gxn = __ldg(gp + 2 * HID);

        float gh0 = 0.f, gh1 = 0.f, gh2 = 0.f;

        if (s > 0) {
            const __nv_bfloat16* hb_rd = hbg + (size_t)((s & 1) ^ 1) * (64 * 512);
            const __nv_bfloat16* hl_rd = hlg + (size_t)((s & 1) ^ 1) * (64 * 512);

            // wait (acquire) for this warp's group producers to finish step s-1
            const unsigned target = 16u * (unsigned)s;
            if (lane == 0) {
                unsigned v;
                do {
                    asm volatile("ld.acquire.gpu.global.u32 %0, [%1];"
                                 : "=r"(v) : "l"(myflag) : "memory");
                } while (v < target);
            }
            __syncwarp();

            // commit group 1: hi slice (8 chunks x 1KB), 16 CP16/lane
#pragma unroll
            for (int it = 0; it < 16; it++) {
                int i = lane + it * 32;              // 0..511
                int chL = i >> 6;                    // 0..7
                int b = (i >> 1) & 31, half = i & 1;
                int ch = w8 + chL;
                const __nv_bfloat16* src = hb_rd + (size_t)ch * 512 + b * 16 + half * 8;
                uint32_t dst = AB_B + (uint32_t)ch * 1024 +
                               (uint32_t)b * 32 + (uint32_t)((half ^ ((b >> 2) & 1)) << 4);
                CP16(dst, src);
            }
            CP_COMMIT();
            // commit group 2: lo slice
#pragma unroll
            for (int it = 0; it < 16; it++) {
                int i = lane + it * 32;
                int chL = i >> 6;
                int b = (i >> 1) & 31, half = i & 1;
                int ch = w8 + chL;
                const __nv_bfloat16* src = hl_rd + (size_t)ch * 512 + b * 16 + half * 8;
                uint32_t dst = AB_B + 65536u + (uint32_t)ch * 1024 +
                               (uint32_t)b * 32 + (uint32_t)((half ^ ((b >> 2) & 1)) << 4);
                CP16(dst, src);
            }
            CP_COMMIT();

            float acc[2][3][4];
#pragma unroll
            for (int mi = 0; mi < 2; mi++)
#pragma unroll
                for (int t3 = 0; t3 < 3; t3++)
#pragma unroll
                    for (int v = 0; v < 4; v++) acc[mi][t3][v] = 0.f;

            // ---- phase 1: hi ready; Ah*Wh + Ah*Wl (lo slice still in flight) ----
            CP_WAIT1();
            __syncwarp();
#pragma unroll
            for (int i = 0; i < 8; i++) {
                const int ch = w8 + i;
                const uint32_t ab = AB_B + (uint32_t)ch * 1024;
                uint32_t aH0[4], aH1[4];
                LDSM_X4(aH0[0], aH0[1], aH0[2], aH0[3], ab + a_off0);
                LDSM_X4(aH1[0], aH1[1], aH1[2], aH1[3], ab + a_off1);
#pragma unroll
                for (int t3 = 0; t3 < 3; t3++) {
                    const int brow = t3 * 8 + (lane & 7);
                    const int bh = (lane >> 3) & 1;
                    uint32_t bH[2], bL[2];
                    const uint32_t bbase = WS_B + 2u * (ch * 384 + brow * 16 +
                                         ((bh ^ ((brow >> 2) & 1)) * 8));
                    LDSM_X2(bH[0], bH[1], bbase);
                    LDSM_X2(bL[0], bL[1], bbase + 2u * 24576);
                    MMA_BF16(acc[0][t3], aH0, bH);
                    MMA_BF16(acc[0][t3], aH0, bL);
                    MMA_BF16(acc[1][t3], aH1, bH);
                    MMA_BF16(acc[1][t3], aH1, bL);
                }
            }

            // ---- phase 2: lo ready; Al*Wh ----
            CP_WAIT0();
            __syncwarp();
#pragma unroll
            for (int i = 0; i < 8; i++) {
                const int ch = w8 + i;
                const uint32_t ab = AB_B + 65536u + (uint32_t)ch * 1024;
                uint32_t aL0[4], aL1[4];
                LDSM_X4(aL0[0], aL0[1], aL0[2], aL0[3], ab + a_off0);
                LDSM_X4(aL1[0], aL1[1], aL1[2], aL1[3], ab + a_off1);
#pragma unroll
                for (int t3 = 0; t3 < 3; t3++) {
                    const int brow = t3 * 8 + (lane & 7);
                    const int bh = (lane >> 3) & 1;
                    uint32_t bH[2];
                    const uint32_t bbase = WS_B + 2u * (ch * 384 + brow * 16 +
                                         ((bh ^ ((brow >> 2) & 1)) * 8));
                    LDSM_X2(bH[0], bH[1], bbase);
                    MMA_BF16(acc[0][t3], aL0, bH);
                    MMA_BF16(acc[1][t3], aL1, bH);
                }
            }
            __syncthreads();   // all warps done with A buffer -> red alias safe

            // cross-warp k reduction via SMEM: red[w][32 b][24 jj]
            const int qid = lane >> 2, qtr = lane & 3;
#pragma unroll
            for (int mi = 0; mi < 2; mi++)
#pragma unroll
                for (int t3 = 0; t3 < 3; t3++) {
                    float* rp = red + wid * 768 + (mi * 16 + qid) * 24 + t3 * 8 + qtr * 2;
                    *(float2*)rp = make_float2(acc[mi][t3][0], acc[mi][t3][1]);
                    *(float2*)(rp + 8 * 24) = make_float2(acc[mi][t3][2], acc[mi][t3][3]);
                }
            __syncthreads();

#pragma unroll
            for (int w2 = 0; w2 < 8; w2++) {
                const float* rp = red + w2 * 768 + eb * 24;
                gh0 += rp[ejj];
                gh1 += rp[8 + ejj];
                gh2 += rp[16 + ejj];
            }
        }

        // gate update for (b=eb, j=ej)
        const float r = 1.f / (1.f + __expf(-(gxr + gh0)));
        const float z = 1.f / (1.f + __expf(-(gxz + gh1)));
        const float npre = fmaf(r, gh2, gxn + gh2);
        const float e2 = __expf(2.f * npre);
        const float n = 1.f - 2.f / (e2 + 1.f);
        const float hnew = (1.f - z) * n + z * hprev;
        hprev = hnew;

        // CRITICAL PATH: only the h broadcast must precede the release
        const __nv_bfloat16 hh = __float2bfloat16(hnew);
        const __nv_bfloat16 hl = __float2bfloat16(hnew - __bfloat162float(hh));
        __nv_bfloat16* hb_wr = hbg + (size_t)(s & 1) * (64 * 512);
        __nv_bfloat16* hl_wr = hlg + (size_t)(s & 1) * (64 * 512);
        const int bidx = (ej >> 4) * 512 + eb * 16 + (ej & 15);
        hb_wr[bidx] = hh;
        hl_wr[bidx] = hl;

        // broadcast stores + red reads done -> release group progress
        __syncthreads();
        if (tid == 0) {
            asm volatile("red.release.gpu.global.add.u32 [%0], 1;"
                         :: "l"(grpflag) : "memory");
        }

        // OFF critical path: GEMM A-splits + final fp32 h (consumed by later kernels)
        const size_t mrow = ((size_t)s * 32 + eb) * HID + ej;
        yh[mrow] = hh;
        yl[mrow] = hl;
        if (s == SEQ - 1)
            y[(size_t)eb * HID + ej] = hnew;
    }

    // reset flags for the next launch/replay (after everyone is done)
    grid_barrier();
    if (tid == 0 && cta < 8)
        *(volatile unsigned*)(sflag + cta * 32) = 0u;
}

// ---------------------------------------------------------------------------
// Tail: new_hidden = stack([h_last0, h_last1])
// ---------------------------------------------------------------------------
__global__ void copy_tail(const float* __restrict__ h0,
                          const float* __restrict__ h1,
                          float* __restrict__ dst)
{
    int i = blockIdx.x * blockDim.x + threadIdx.x;
    dst[i]               = h0[i];
    dst[BATCH * HID + i] = h1[i];
}

// ---------------------------------------------------------------------------
// kernel_launch
// ---------------------------------------------------------------------------
extern "C" void kernel_launch(void* const* d_in, const int* in_sizes, int n_in,
                              void* d_out, int out_size)
{
    const float* x    = (const float*)d_in[0];
    const float* Wih0 = (const float*)d_in[1];
    const float* Whh0 = (const float*)d_in[2];
    const float* b0   = (const float*)d_in[3];
    const float* Wih1 = (const float*)d_in[4];
    const float* Whh1 = (const float*)d_in[5];
    const float* b1   = (const float*)d_in[6];
    const float* Wlin = (const float*)d_in[7];
    const float* blin = (const float*)d_in[8];
    float* out = (float*)d_out;

    float *gx, *y0, *y1;
    __nv_bfloat16 *ah, *al, *wh, *wl, *hb, *hl;
    unsigned *sf0, *sf1;
    cudaGetSymbolAddress((void**)&gx, g_gx);
    cudaGetSymbolAddress((void**)&y0, g_y0);
    cudaGetSymbolAddress((void**)&y1, g_y1);
    cudaGetSymbolAddress((void**)&ah, g_ah);
    cudaGetSymbolAddress((void**)&al, g_al);
    cudaGetSymbolAddress((void**)&wh, g_wh);
    cudaGetSymbolAddress((void**)&wl, g_wl);
    cudaGetSymbolAddress((void**)&hb, g_hb);
    cudaGetSymbolAddress((void**)&hl, g_hl);
    cudaGetSymbolAddress((void**)&sf0, g_sflag0);
    cudaGetSymbolAddress((void**)&sf1, g_sflag1);

    cudaFuncSetAttribute(gemm_mma, cudaFuncAttributeMaxDynamicSharedMemorySize, GEMM_SMEM);
    cudaFuncSetAttribute(gru_scan_mma, cudaFuncAttributeMaxDynamicSharedMemorySize, SCAN_SMEM);

    const int M = SEQ * BATCH;   // 16384

    // ---- layer 0 input GEMM: gx = x @ Wih0^T + b0 (time-major rows) ----
    conv_split<<<2048, 256>>>(x, IN_D, SEQ * IN_D, 9, (size_t)M * IN_D, ah, al);
    conv_split<<<2048, 256>>>(Wih0, 32 * IN_D, IN_D, 9, (size_t)G3 * IN_D, wh, wl);
    gemm_mma<<<dim3(G3 / 128, M / 128), 256, GEMM_SMEM>>>(
        ah, al, wh, wl, b0, gx, IN_D, 32 * G3, G3);

    // ---- layer-0 scan (y pointer = last-step slot only) ----
    gru_scan_mma<<<NCTA, 256, SCAN_SMEM>>>(gx, Whh0, y0, ah, al, hb, hl, sf0);

    // ---- layer 1 input GEMM: gx = y0 @ Wih1^T + b1 (A splits from scan) ----
    conv_split<<<2048, 256>>>(Wih1, 32 * HID, HID, 10, (size_t)G3 * HID, wh, wl);
    gemm_mma<<<dim3(G3 / 128, M / 128), 256, GEMM_SMEM>>>(
        ah, al, wh, wl, b1, gx, HID, 32 * G3, G3);

    // ---- layer-1 scan ----
    gru_scan_mma<<<NCTA, 256, SCAN_SMEM>>>(gx, Whh1, y1, ah, al, hb, hl, sf1);

    // ---- output GEMM: out[b][t][:] = y1 @ Wlin^T + blin ----
    conv_split<<<2048, 256>>>(Wlin, 32 * HID, HID, 10, (size_t)IN_D * HID, wh, wl);
    gemm_mma<<<dim3(IN_D / 128, M / 128), 256, GEMM_SMEM>>>(
        ah, al, wh, wl, blin, out, HID, IN_D, SEQ * IN_D);

    copy_tail<<<128, 256>>>(y0, y1, out + (size_t)BATCH * SEQ * IN_D);
}